// round 4
// baseline (speedup 1.0000x reference)
#include <cuda_runtime.h>

#define W 224
#define WW (W * W)                  // 50176
#define F4_PER (WW / 4)             // 12544 float4 per sample
#define F4_PER_ROW (W / 4)          // 56
#define NSAMP 256
#define F4_TOTAL (NSAMP * F4_PER)   // 3,211,264
#define BLK_PER_SAMP 7
#define NBLK1 (NSAMP * BLK_PER_SAMP)        // 1792
#define F4_PER_BLK (F4_PER / BLK_PER_SAMP)  // 1792 = 256 thr * 7 f4
#define NBLK2 (F4_TOTAL / 1024)             // 3136

// Scratch (device globals; zero-init at load; g_acc/g_cnt reset by last block)
__device__ int4     g_blk[NBLK1];   // per-block {maxbits, cnt, si, sj}
__device__ double   g_acc;
__device__ unsigned g_cnt;

// ---------------------------------------------------------------------------
// Kernel 1: per-block max + tie stats in ONE pass (ties counted from registers).
// grid = 1792 (7 blocks/sample), 256 threads, 7 float4 per thread.
// ---------------------------------------------------------------------------
__global__ __launch_bounds__(256) void k_maxstats(const float* __restrict__ tgt) {
    const int b = blockIdx.x / BLK_PER_SAMP;
    const int c = blockIdx.x - b * BLK_PER_SAMP;
    const int tid = threadIdx.x;
    const float4* __restrict__ t4 =
        reinterpret_cast<const float4*>(tgt) + (size_t)b * F4_PER + c * F4_PER_BLK;

    // Front-batched loads into registers (MLP = 7)
    float4 v[7];
    #pragma unroll
    for (int k = 0; k < 7; k++) v[k] = t4[k * 256 + tid];

    // Thread max, branch-free
    float tmax = -3.0e38f;
    #pragma unroll
    for (int k = 0; k < 7; k++)
        tmax = fmaxf(tmax, fmaxf(fmaxf(v[k].x, v[k].y), fmaxf(v[k].z, v[k].w)));

    // Block max
    float m = tmax;
    #pragma unroll
    for (int o = 16; o > 0; o >>= 1)
        m = fmaxf(m, __shfl_xor_sync(0xffffffffu, m, o));

    __shared__ float smax[8];
    __shared__ float sM;
    __shared__ int scnt, ssi, ssj;
    const int wid = tid >> 5, lid = tid & 31;
    if (lid == 0) smax[wid] = m;
    if (tid == 0) { scnt = 0; ssi = 0; ssj = 0; }
    __syncthreads();
    if (tid == 0) {
        float bm = smax[0];
        #pragma unroll
        for (int w = 1; w < 8; w++) bm = fmaxf(bm, smax[w]);
        sM = bm;
    }
    __syncthreads();
    const float M = sM;

    // Tie stats from registers — only threads holding the block max participate
    if (tmax == M) {
        int cnt = 0, si = 0, sj = 0;
        #pragma unroll
        for (int k = 0; k < 7; k++) {
            const int r4 = c * F4_PER_BLK + k * 256 + tid;  // f4 idx within sample
            const int i  = r4 / F4_PER_ROW;
            const int j0 = (r4 - i * F4_PER_ROW) * 4;
            if (v[k].x == M) { cnt++; si += i; sj += j0;     }
            if (v[k].y == M) { cnt++; si += i; sj += j0 + 1; }
            if (v[k].z == M) { cnt++; si += i; sj += j0 + 2; }
            if (v[k].w == M) { cnt++; si += i; sj += j0 + 3; }
        }
        atomicAdd_block(&scnt, cnt);
        atomicAdd_block(&ssi,  si);
        atomicAdd_block(&ssj,  sj);
    }
    __syncthreads();

    if (tid == 0) {
        const unsigned mb = __float_as_uint(M);   // M >= 0 -> bit order == float order
        g_blk[blockIdx.x] = make_int4((int)mb, scnt, ssi, ssj);
    }
}

// ---------------------------------------------------------------------------
// Kernel 2: centroid (from g_blk, per block) + weighted BCE + grid finalize.
// grid = 3136 blocks, 256 thr, 4 coalesced float4/thread.
// Last block writes out[0] and resets accumulators (graph-replay safe).
// ---------------------------------------------------------------------------
__global__ __launch_bounds__(256) void k_loss(const float* __restrict__ inp,
                                              const float* __restrict__ tgt,
                                              float* __restrict__ out,
                                              double invn) {
    const int b = blockIdx.x / (NBLK2 / NSAMP);   // 3136/256 blocks per sample... 
    // NOTE: NBLK2/NSAMP = 12.25 — not integral; derive sample from f4 index instead.
    (void)b;

    __shared__ float2 sxy;
    // Sample of this block: all 1024 f4 of a block lie within one sample since
    // F4_PER (12544) is NOT a multiple of 1024 — so compute from first f4 idx,
    // and guard per-element below for blocks straddling a sample boundary.
    if (threadIdx.x == 0) {
        const int p0   = blockIdx.x * 1024;
        const int samp = p0 / F4_PER;
        unsigned mb = 0u;
        int4 e[BLK_PER_SAMP];
        #pragma unroll
        for (int c = 0; c < BLK_PER_SAMP; c++) e[c] = g_blk[samp * BLK_PER_SAMP + c];
        #pragma unroll
        for (int c = 0; c < BLK_PER_SAMP; c++) mb = max(mb, (unsigned)e[c].x);
        int cnt = 0, si = 0, sj = 0;
        #pragma unroll
        for (int c = 0; c < BLK_PER_SAMP; c++)
            if ((unsigned)e[c].x == mb) { cnt += e[c].y; si += e[c].z; sj += e[c].w; }
        const float inv = 1.0f / (float)cnt;
        sxy = make_float2((float)si * inv, (float)sj * inv);
    }
    __syncthreads();

    const float4* __restrict__ p4 = reinterpret_cast<const float4*>(inp);
    const float4* __restrict__ t4 = reinterpret_cast<const float4*>(tgt);
    const int samp0 = (blockIdx.x * 1024) / F4_PER;

    float s = 0.0f;
    #pragma unroll
    for (int k = 0; k < 4; k++) {
        const int p = blockIdx.x * 1024 + k * 256 + threadIdx.x;   // global f4 idx
        float4 pv = __ldcs(p4 + p);        // streaming: don't pollute L2
        float4 tv = t4[p];                 // expect L2 hit

        const int bb = p / F4_PER;
        const int r  = p - bb * F4_PER;
        const int i  = r / F4_PER_ROW;
        const int j0 = (r - i * F4_PER_ROW) * 4;

        float2 xy;
        if (bb == samp0) {
            xy = sxy;                       // common fast path (shared broadcast)
        } else {
            // Block straddles a sample boundary: recompute for this sample.
            unsigned mb = 0u; int cnt = 0, si = 0, sj = 0;
            #pragma unroll
            for (int c = 0; c < BLK_PER_SAMP; c++)
                mb = max(mb, (unsigned)g_blk[bb * BLK_PER_SAMP + c].x);
            #pragma unroll
            for (int c = 0; c < BLK_PER_SAMP; c++) {
                int4 e = g_blk[bb * BLK_PER_SAMP + c];
                if ((unsigned)e.x == mb) { cnt += e.y; si += e.z; sj += e.w; }
            }
            const float inv = 1.0f / (float)cnt;
            xy = make_float2((float)si * inv, (float)sj * inv);
        }

        const float di  = (float)i - xy.x;
        const float di2 = di * di;

        float pe[4] = {pv.x, pv.y, pv.z, pv.w};
        float te[4] = {tv.x, tv.y, tv.z, tv.w};
        #pragma unroll
        for (int e = 0; e < 4; e++) {
            float dj  = (float)(j0 + e) - xy.y;
            float wgt = __fdividef((float)W, sqrtf(fmaf(dj, dj, di2)) + 1.0f);
            float lp  = fmaxf(__logf(pe[e]),        -100.0f);
            float lq  = fmaxf(__logf(1.0f - pe[e]), -100.0f);
            s += wgt * (-(te[e] * lp + (1.0f - te[e]) * lq));
        }
    }

    #pragma unroll
    for (int o = 16; o > 0; o >>= 1)
        s += __shfl_xor_sync(0xffffffffu, s, o);

    __shared__ float sw[8];
    const int wid = threadIdx.x >> 5, lid = threadIdx.x & 31;
    if (lid == 0) sw[wid] = s;
    __syncthreads();
    if (threadIdx.x == 0) {
        float bs = sw[0];
        #pragma unroll
        for (int w = 1; w < 8; w++) bs += sw[w];
        atomicAdd(&g_acc, (double)bs);
        __threadfence();
        const unsigned ticket = atomicAdd(&g_cnt, 1u);
        if (ticket == NBLK2 - 1) {          // last block: finalize + reset
            const double total = atomicAdd(&g_acc, 0.0);
            out[0] = (float)(total * invn);
            g_acc = 0.0;
            g_cnt = 0u;
        }
    }
}

extern "C" void kernel_launch(void* const* d_in, const int* in_sizes, int n_in,
                              void* d_out, int out_size) {
    const float* inp = (const float*)d_in[0];
    const float* tgt = (const float*)d_in[1];
    float* out = (float*)d_out;

    k_maxstats<<<NBLK1, 256>>>(tgt);
    k_loss<<<NBLK2, 256>>>(inp, tgt, out, 1.0 / (double)((size_t)NSAMP * WW));
}

// round 5
// speedup vs baseline: 1.0602x; 1.0602x over previous
#include <cuda_runtime.h>

#define W 224
#define WW (W * W)                  // 50176
#define F4_PER (WW / 4)             // 12544 float4 per sample
#define F4_PER_ROW (W / 4)          // 56
#define NSAMP 256
#define BLK_PER_SAMP 7
#define NBLK1 (NSAMP * BLK_PER_SAMP)        // 1792
#define F4_PER_BLK (F4_PER / BLK_PER_SAMP)  // 1792 = 256 thr * 7 f4
#define NBLK2 NBLK1                          // 1792 loss blocks too

// Scratch (device globals; zero-init at load; g_acc/g_cnt reset by last block)
__device__ int4     g_blk[NBLK1];   // per-block {maxbits, cnt, si, sj}
__device__ double   g_acc;
__device__ unsigned g_cnt;

// ---------------------------------------------------------------------------
// Kernel 1: per-block max + tie stats in ONE pass (ties counted from registers).
// grid = 1792 (7 blocks/sample), 256 threads, 7 float4 per thread.
// ---------------------------------------------------------------------------
__global__ __launch_bounds__(256) void k_maxstats(const float* __restrict__ tgt) {
    const int b = blockIdx.x / BLK_PER_SAMP;
    const int c = blockIdx.x - b * BLK_PER_SAMP;
    const int tid = threadIdx.x;
    const float4* __restrict__ t4 =
        reinterpret_cast<const float4*>(tgt) + (size_t)b * F4_PER + c * F4_PER_BLK;

    float4 v[7];
    #pragma unroll
    for (int k = 0; k < 7; k++) v[k] = t4[k * 256 + tid];

    float tmax = -3.0e38f;
    #pragma unroll
    for (int k = 0; k < 7; k++)
        tmax = fmaxf(tmax, fmaxf(fmaxf(v[k].x, v[k].y), fmaxf(v[k].z, v[k].w)));

    float m = tmax;
    #pragma unroll
    for (int o = 16; o > 0; o >>= 1)
        m = fmaxf(m, __shfl_xor_sync(0xffffffffu, m, o));

    __shared__ float smax[8];
    __shared__ float sM;
    __shared__ int scnt, ssi, ssj;
    const int wid = tid >> 5, lid = tid & 31;
    if (lid == 0) smax[wid] = m;
    if (tid == 0) { scnt = 0; ssi = 0; ssj = 0; }
    __syncthreads();
    if (tid == 0) {
        float bm = smax[0];
        #pragma unroll
        for (int w = 1; w < 8; w++) bm = fmaxf(bm, smax[w]);
        sM = bm;
    }
    __syncthreads();
    const float M = sM;

    if (tmax == M) {   // rare: only threads holding the block max
        int cnt = 0, si = 0, sj = 0;
        #pragma unroll
        for (int k = 0; k < 7; k++) {
            const int r4 = c * F4_PER_BLK + k * 256 + tid;
            const int i  = r4 / F4_PER_ROW;
            const int j0 = (r4 - i * F4_PER_ROW) * 4;
            if (v[k].x == M) { cnt++; si += i; sj += j0;     }
            if (v[k].y == M) { cnt++; si += i; sj += j0 + 1; }
            if (v[k].z == M) { cnt++; si += i; sj += j0 + 2; }
            if (v[k].w == M) { cnt++; si += i; sj += j0 + 3; }
        }
        atomicAdd_block(&scnt, cnt);
        atomicAdd_block(&ssi,  si);
        atomicAdd_block(&ssj,  sj);
    }
    __syncthreads();

    if (tid == 0) {
        const unsigned mb = __float_as_uint(M);   // target >= 0 -> bit order == float order
        g_blk[blockIdx.x] = make_int4((int)mb, scnt, ssi, ssj);
    }
}

// ---------------------------------------------------------------------------
// Kernel 2: weighted BCE. grid = (7, 256): y = sample, x = chunk.
// Block never straddles a sample -> centroid uniform per block, fully hoisted.
// Last block finalizes out[0] and resets accumulators (graph-replay safe).
// ---------------------------------------------------------------------------
__global__ __launch_bounds__(256) void k_loss(const float* __restrict__ inp,
                                              const float* __restrict__ tgt,
                                              float* __restrict__ out,
                                              double invn) {
    const int samp = blockIdx.y;
    const int c    = blockIdx.x;
    const int tid  = threadIdx.x;

    __shared__ float2 sxy;
    if (tid == 0) {
        int4 e[BLK_PER_SAMP];
        #pragma unroll
        for (int q = 0; q < BLK_PER_SAMP; q++) e[q] = g_blk[samp * BLK_PER_SAMP + q];
        unsigned mb = 0u;
        #pragma unroll
        for (int q = 0; q < BLK_PER_SAMP; q++) mb = max(mb, (unsigned)e[q].x);
        int cnt = 0, si = 0, sj = 0;
        #pragma unroll
        for (int q = 0; q < BLK_PER_SAMP; q++)
            if ((unsigned)e[q].x == mb) { cnt += e[q].y; si += e[q].z; sj += e[q].w; }
        const float inv = 1.0f / (float)cnt;
        sxy = make_float2((float)si * inv, (float)sj * inv);
    }
    __syncthreads();
    const float cx = sxy.x, cy = sxy.y;

    const size_t base = (size_t)samp * F4_PER + c * F4_PER_BLK;
    const float4* __restrict__ p4 = reinterpret_cast<const float4*>(inp) + base;
    const float4* __restrict__ t4 = reinterpret_cast<const float4*>(tgt) + base;

    float s = 0.0f;
    #pragma unroll
    for (int k = 0; k < 7; k++) {
        const int r4 = c * F4_PER_BLK + k * 256 + tid;   // f4 idx within sample
        float4 pv = p4[k * 256 + tid];
        float4 tv = t4[k * 256 + tid];

        const int i  = r4 / F4_PER_ROW;
        const int j0 = (r4 - i * F4_PER_ROW) * 4;
        const float di  = (float)i - cx;
        const float di2 = di * di;
        const float dj0 = (float)j0 - cy;

        float pe[4] = {pv.x, pv.y, pv.z, pv.w};
        float te[4] = {tv.x, tv.y, tv.z, tv.w};
        #pragma unroll
        for (int e = 0; e < 4; e++) {
            float dj  = dj0 + (float)e;
            float wgt = __fdividef((float)W, sqrtf(fmaf(dj, dj, di2)) + 1.0f);
            float lp  = fmaxf(__logf(pe[e]),        -100.0f);
            float lq  = fmaxf(__logf(1.0f - pe[e]), -100.0f);
            s += wgt * (-(te[e] * lp + (1.0f - te[e]) * lq));
        }
    }

    #pragma unroll
    for (int o = 16; o > 0; o >>= 1)
        s += __shfl_xor_sync(0xffffffffu, s, o);

    __shared__ float sw[8];
    const int wid = tid >> 5, lid = tid & 31;
    if (lid == 0) sw[wid] = s;
    __syncthreads();
    if (tid == 0) {
        float bs = sw[0];
        #pragma unroll
        for (int w = 1; w < 8; w++) bs += sw[w];
        atomicAdd(&g_acc, (double)bs);
        __threadfence();
        const unsigned ticket = atomicAdd(&g_cnt, 1u);
        if (ticket == NBLK2 - 1) {          // last block: finalize + reset
            const double total = atomicAdd(&g_acc, 0.0);
            out[0] = (float)(total * invn);
            g_acc = 0.0;
            g_cnt = 0u;
        }
    }
}

extern "C" void kernel_launch(void* const* d_in, const int* in_sizes, int n_in,
                              void* d_out, int out_size) {
    const float* inp = (const float*)d_in[0];
    const float* tgt = (const float*)d_in[1];
    float* out = (float*)d_out;

    k_maxstats<<<NBLK1, 256>>>(tgt);
    dim3 g2(BLK_PER_SAMP, NSAMP);
    k_loss<<<g2, 256>>>(inp, tgt, out, 1.0 / (double)((size_t)NSAMP * WW));
}